// round 4
// baseline (speedup 1.0000x reference)
#include <cuda_runtime.h>
#include <math.h>

// Fixed by the model architecture (hidden widths):
#define HID   16
#define HID2  8
#define BN_EPS 1e-5f

// Capacity limits for static scratch (host clamps against these).
#define N_MAX    1048576
#define POOL_CAP (3 * 4194304)   // 3 * NG*DT pool slots

// ---------------- scratch (static __device__, float4-typed => 16B aligned) ----------------
__device__ float4   g_pre [N_MAX * 4];   // 16 floats/node; also aliased as agg target for layer2 (stride 4)
__device__ float4   g_h0  [N_MAX * 4];
__device__ float4   g_h1  [N_MAX * 4];
__device__ float4   g_h2  [N_MAX * 2];
__device__ float4   g_agg [N_MAX * 4];
__device__ float    g_ssum[HID];
__device__ float    g_ssq [HID];
__device__ float    g_scale[HID];
__device__ float    g_shift[HID];
__device__ unsigned g_pool[POOL_CAP];

// ---------------- helpers ----------------
__device__ __forceinline__ float gelu_exact(float v) {
    return 0.5f * v * (1.0f + erff(v * 0.7071067811865476f));
}
__device__ __forceinline__ unsigned enc_f(float f) {
    unsigned u = __float_as_uint(f);
    return (u & 0x80000000u) ? ~u : (u | 0x80000000u);
}
__device__ __forceinline__ float dec_f(unsigned u) {
    return (u & 0x80000000u) ? __uint_as_float(u & 0x7FFFFFFFu)
                             : __uint_as_float(~u);
}

template <int C>
__device__ __forceinline__ void warp_stats(const float* acc) {
#pragma unroll
    for (int j = 0; j < C; j++) {
        float v = acc[j];
        float q = v * v;
#pragma unroll
        for (int o = 16; o > 0; o >>= 1) {
            v += __shfl_xor_sync(0xffffffffu, v, o);
            q += __shfl_xor_sync(0xffffffffu, q, o);
        }
        if ((threadIdx.x & 31) == 0) {
            atomicAdd(&g_ssum[j], v);
            atomicAdd(&g_ssq[j],  q);
        }
    }
}

// ---------------- init ----------------
__global__ void k_init(int pool_n) {
    int i = blockIdx.x * blockDim.x + threadIdx.x;
    if (i < HID) { g_ssum[i] = 0.f; g_ssq[i] = 0.f; }
    if (i < pool_n) g_pool[i] = 0u;   // 0 < enc(any finite float)
}

__global__ void k_zero_agg(int n4) {
    int i = blockIdx.x * blockDim.x + threadIdx.x;
    if (i < n4) g_agg[i] = make_float4(0.f, 0.f, 0.f, 0.f);
}

// ---------------- layer 0 GEMM: pre = x @ W0 + b0, + BN stats ----------------
__global__ __launch_bounds__(256) void k_gemm0(const float* __restrict__ x,
                                               const float* __restrict__ W0,
                                               const float* __restrict__ b0,
                                               int N, int F) {
    extern __shared__ float Ws[];            // F*16 floats (dynamic)
    __shared__ float bs[HID];
    int tid = threadIdx.x;
    int wtot = F * HID;
    for (int i = tid; i < wtot; i += 256) Ws[i] = W0[i];
    if (tid < HID) bs[tid] = b0[tid];
    __syncthreads();

    int r = blockIdx.x * 256 + tid;
    bool act = r < N;
    float acc[HID];
#pragma unroll
    for (int q = 0; q < HID; q++) acc[q] = act ? bs[q] : 0.f;

    if (act) {
        const float4* xr = (const float4*)(x + (size_t)r * F);
        int F4 = F >> 2;
#pragma unroll 4
        for (int c4 = 0; c4 < F4; c4++) {
            float4 xv = __ldg(xr + c4);
#pragma unroll
            for (int u = 0; u < 4; u++) {
                float xs = (&xv.x)[u];
                const float4* wr = (const float4*)&Ws[(c4 * 4 + u) * HID];
                float4 w;
                w = wr[0]; acc[0] += xs * w.x; acc[1] += xs * w.y; acc[2]  += xs * w.z; acc[3]  += xs * w.w;
                w = wr[1]; acc[4] += xs * w.x; acc[5] += xs * w.y; acc[6]  += xs * w.z; acc[7]  += xs * w.w;
                w = wr[2]; acc[8] += xs * w.x; acc[9] += xs * w.y; acc[10] += xs * w.z; acc[11] += xs * w.w;
                w = wr[3]; acc[12]+= xs * w.x; acc[13]+= xs * w.y; acc[14] += xs * w.z; acc[15] += xs * w.w;
            }
        }
        g_pre[(size_t)r * 4 + 0] = make_float4(acc[0],  acc[1],  acc[2],  acc[3]);
        g_pre[(size_t)r * 4 + 1] = make_float4(acc[4],  acc[5],  acc[6],  acc[7]);
        g_pre[(size_t)r * 4 + 2] = make_float4(acc[8],  acc[9],  acc[10], acc[11]);
        g_pre[(size_t)r * 4 + 3] = make_float4(acc[12], acc[13], acc[14], acc[15]);
    }
    warp_stats<HID>(acc);
}

// ---------------- BN stats finalize ----------------
__global__ void k_finalize(int C, const float* __restrict__ gam,
                           const float* __restrict__ bet, int N) {
    int j = threadIdx.x;
    if (j < C) {
        float inv_n = 1.0f / (float)N;
        float mean = g_ssum[j] * inv_n;
        float var  = g_ssq[j] * inv_n - mean * mean;
        float istd = rsqrtf(var + BN_EPS);
        float sc   = gam[j] * istd;
        g_scale[j] = sc;
        g_shift[j] = bet[j] - mean * sc;
        g_ssum[j]  = 0.f;
        g_ssq[j]   = 0.f;
    }
}

// ---------------- BN apply kernels ----------------
__global__ void k_bn0(int N) {  // + GELU -> g_h0
    int n = blockIdx.x * blockDim.x + threadIdx.x;
    if (n >= N) return;
#pragma unroll
    for (int q = 0; q < 4; q++) {
        float4 v = g_pre[(size_t)n * 4 + q]; float4 r;
        r.x = gelu_exact(v.x * g_scale[q*4+0] + g_shift[q*4+0]);
        r.y = gelu_exact(v.y * g_scale[q*4+1] + g_shift[q*4+1]);
        r.z = gelu_exact(v.z * g_scale[q*4+2] + g_shift[q*4+2]);
        r.w = gelu_exact(v.w * g_scale[q*4+3] + g_shift[q*4+3]);
        g_h0[(size_t)n * 4 + q] = r;
    }
}

__global__ void k_bn1(int N) {  // no activation -> g_h1
    int n = blockIdx.x * blockDim.x + threadIdx.x;
    if (n >= N) return;
#pragma unroll
    for (int q = 0; q < 4; q++) {
        float4 v = g_pre[(size_t)n * 4 + q]; float4 r;
        r.x = v.x * g_scale[q*4+0] + g_shift[q*4+0];
        r.y = v.y * g_scale[q*4+1] + g_shift[q*4+1];
        r.z = v.z * g_scale[q*4+2] + g_shift[q*4+2];
        r.w = v.w * g_scale[q*4+3] + g_shift[q*4+3];
        g_h1[(size_t)n * 4 + q] = r;
    }
}

__global__ void k_bn2(float* __restrict__ outH, int N) {  // C=8 -> g_h2 (+ output h if present)
    int n = blockIdx.x * blockDim.x + threadIdx.x;
    if (n >= N) return;
#pragma unroll
    for (int q = 0; q < 2; q++) {
        // layer-2 pre stored at node stride 4 float4s (first 2 used)
        float4 v = g_pre[(size_t)n * 4 + q]; float4 r;
        r.x = v.x * g_scale[q*4+0] + g_shift[q*4+0];
        r.y = v.y * g_scale[q*4+1] + g_shift[q*4+1];
        r.z = v.z * g_scale[q*4+2] + g_shift[q*4+2];
        r.w = v.w * g_scale[q*4+3] + g_shift[q*4+3];
        g_h2[(size_t)n * 2 + q] = r;
        if (outH) {
            float* o = outH + (size_t)n * 8 + q * 4;
            o[0] = r.x; o[1] = r.y; o[2] = r.z; o[3] = r.w;
        }
    }
}

// ---------------- edge scatter-add: agg[dst] += h[src] ----------------
__global__ void k_edge(const int* __restrict__ ei, int layer, int N, int E) {
    int idx = blockIdx.x * blockDim.x + threadIdx.x;
    if (idx >= 4 * E) return;
    int e = idx >> 2, q = idx & 3;
    const float4* h = layer ? g_h1 : g_h0;
    int s = __ldg(ei + e);
    int d = __ldg(ei + E + e);
    if ((unsigned)s >= (unsigned)N || (unsigned)d >= (unsigned)N) return;  // safety guard
    float4 v = h[(size_t)s * 4 + q];
    atomicAdd(&g_agg[(size_t)d * 4 + q], v);
}

// ---------------- GIN small GEMM: pre = (h + agg) @ W + b, + stats ----------------
template <int C>
__global__ __launch_bounds__(256) void k_gin(const float* __restrict__ W,
                                             const float* __restrict__ b, int N) {
    __shared__ float Wsh[HID * C];
    __shared__ float bs[C];
    int tid = threadIdx.x;
    for (int i = tid; i < HID * C; i += 256) Wsh[i] = W[i];
    if (tid < C) bs[tid] = b[tid];
    __syncthreads();

    const float4* hin = (C == HID) ? g_h0 : g_h1;
    int n = blockIdx.x * 256 + tid;
    bool act = n < N;
    float acc[C];
#pragma unroll
    for (int j = 0; j < C; j++) acc[j] = 0.f;

    if (act) {
        float t[HID];
#pragma unroll
        for (int q = 0; q < 4; q++) {
            float4 a = hin[(size_t)n * 4 + q];
            float4 b4 = g_agg[(size_t)n * 4 + q];
            t[q*4+0] = a.x + b4.x; t[q*4+1] = a.y + b4.y;
            t[q*4+2] = a.z + b4.z; t[q*4+3] = a.w + b4.w;
        }
#pragma unroll
        for (int j = 0; j < C; j++) acc[j] = bs[j];
#pragma unroll
        for (int k = 0; k < HID; k++) {
            float tv = t[k];
#pragma unroll
            for (int j = 0; j < C; j++) acc[j] += tv * Wsh[k * C + j];
        }
        // node stride is 4 float4s regardless of C (C=8 uses first 2)
#pragma unroll
        for (int q = 0; q < C / 4; q++) {
            float4 r = make_float4(acc[q*4+0], acc[q*4+1], acc[q*4+2], acc[q*4+3]);
            g_pre[(size_t)n * 4 + q] = r;
        }
    }
    warp_stats<C>(acc);
}

// ---------------- fused z0/z1/z2: Z_sum write + 3x segment_max ----------------
#define CHB 256
#define STR 260
__global__ __launch_bounds__(512) void k_bigz(const float* __restrict__ Wl0, const float* __restrict__ bl0,
                                              const float* __restrict__ Wl1, const float* __restrict__ bl1,
                                              const float* __restrict__ Wl2, const float* __restrict__ bl2,
                                              const int*   __restrict__ batch,
                                              float* __restrict__ Zs,
                                              int N, int DT, int NG) {
    __shared__ __align__(16) float sh[40 * STR];
    __shared__ int shb[CHB];
    int tid = threadIdx.x;
    int j = blockIdx.y * 512 + tid;   // feature index
    bool fj = j < DT;

    float w0[HID], w1[HID], w2[HID2];
    float bb0 = 0.f, bb1 = 0.f, bb2 = 0.f;
    if (fj) {
#pragma unroll
        for (int k = 0; k < HID; k++) { w0[k] = Wl0[k * DT + j]; w1[k] = Wl1[k * DT + j]; }
#pragma unroll
        for (int k = 0; k < HID2; k++) w2[k] = Wl2[k * DT + j];
        bb0 = bl0[j]; bb1 = bl1[j]; bb2 = bl2[j];
    }

    int n0 = blockIdx.x * CHB;
    int valid = N - n0; if (valid > CHB) valid = CHB;

    const float* h0f = (const float*)g_h0;
    const float* h1f = (const float*)g_h1;
    const float* h2f = (const float*)g_h2;
    for (int idx = tid; idx < valid * 16; idx += 512) {
        int n = idx >> 4, k = idx & 15;
        sh[k * STR + n]        = h0f[(size_t)(n0 + n) * 16 + k];
        sh[(16 + k) * STR + n] = h1f[(size_t)(n0 + n) * 16 + k];
    }
    for (int idx = tid; idx < valid * 8; idx += 512) {
        int n = idx >> 3, k = idx & 7;
        sh[(32 + k) * STR + n] = h2f[(size_t)(n0 + n) * 8 + k];
    }
    if (tid < valid) shb[tid] = batch[n0 + tid];
    __syncthreads();
    if (!fj) return;

    const float NINF = __int_as_float(0xff800000);
    int cg = -1;
    float m0 = NINF, m1 = NINF, m2 = NINF;

    for (int nl = 0; nl < valid; nl += 4) {
        float a0[4], a1[4], a2[4];
#pragma unroll
        for (int i = 0; i < 4; i++) { a0[i] = bb0; a1[i] = bb1; a2[i] = bb2; }
#pragma unroll
        for (int k = 0; k < HID; k++) {
            float4 hv = *(const float4*)&sh[k * STR + nl];
            a0[0] += hv.x * w0[k]; a0[1] += hv.y * w0[k];
            a0[2] += hv.z * w0[k]; a0[3] += hv.w * w0[k];
        }
#pragma unroll
        for (int k = 0; k < HID; k++) {
            float4 hv = *(const float4*)&sh[(16 + k) * STR + nl];
            a1[0] += hv.x * w1[k]; a1[1] += hv.y * w1[k];
            a1[2] += hv.z * w1[k]; a1[3] += hv.w * w1[k];
        }
#pragma unroll
        for (int k = 0; k < HID2; k++) {
            float4 hv = *(const float4*)&sh[(32 + k) * STR + nl];
            a2[0] += hv.x * w2[k]; a2[1] += hv.y * w2[k];
            a2[2] += hv.z * w2[k]; a2[3] += hv.w * w2[k];
        }
#pragma unroll
        for (int i = 0; i < 4; i++) {
            if (nl + i >= valid) break;
            float z0 = gelu_exact(a0[i]);
            float z1 = a1[i], z2 = a2[i];
            if (Zs) Zs[(size_t)(n0 + nl + i) * DT + j] = z0 + z1 + z2;
            int g = shb[nl + i];
            if (g != cg) {
                if ((unsigned)cg < (unsigned)NG) {
                    atomicMax(&g_pool[(size_t)cg * DT + j],            enc_f(m0));
                    atomicMax(&g_pool[((size_t)NG + cg) * DT + j],     enc_f(m1));
                    atomicMax(&g_pool[((size_t)2 * NG + cg) * DT + j], enc_f(m2));
                }
                cg = g; m0 = NINF; m1 = NINF; m2 = NINF;
            }
            m0 = fmaxf(m0, z0); m1 = fmaxf(m1, z1); m2 = fmaxf(m2, z2);
        }
    }
    if ((unsigned)cg < (unsigned)NG) {
        atomicMax(&g_pool[(size_t)cg * DT + j],            enc_f(m0));
        atomicMax(&g_pool[((size_t)NG + cg) * DT + j],     enc_f(m1));
        atomicMax(&g_pool[((size_t)2 * NG + cg) * DT + j], enc_f(m2));
    }
}

// ---------------- pooled output ----------------
__global__ void k_out(float* __restrict__ out, int DT, int NG) {
    int g = blockIdx.x;
    for (int j = threadIdx.x; j < DT; j += blockDim.x) {
        out[(size_t)g * DT + j] = dec_f(g_pool[(size_t)g * DT + j])
                                + dec_f(g_pool[((size_t)NG + g) * DT + j])
                                + dec_f(g_pool[((size_t)2 * NG + g) * DT + j]);
    }
}

// ---------------- launch ----------------
extern "C" void kernel_launch(void* const* d_in, const int* in_sizes, int n_in,
                              void* d_out, int out_size) {
    const float* x   = (const float*)d_in[0];
    const int*   ei  = (const int*)  d_in[1];
    const int*   bat = (const int*)  d_in[2];
    const float* W0  = (const float*)d_in[3];
    const float* b0  = (const float*)d_in[4];
    const float* g0  = (const float*)d_in[5];
    const float* be0 = (const float*)d_in[6];
    const float* Wl0 = (const float*)d_in[7];
    const float* bl0 = (const float*)d_in[8];
    const float* W1  = (const float*)d_in[9];
    const float* b1  = (const float*)d_in[10];
    const float* g1  = (const float*)d_in[11];
    const float* be1 = (const float*)d_in[12];
    const float* Wl1 = (const float*)d_in[13];
    const float* bl1 = (const float*)d_in[14];
    const float* W2  = (const float*)d_in[15];
    const float* b2  = (const float*)d_in[16];
    const float* g2  = (const float*)d_in[17];
    const float* be2 = (const float*)d_in[18];
    const float* Wl2 = (const float*)d_in[19];
    const float* bl2 = (const float*)d_in[20];

    // ---- derive shapes from in_sizes (never trust compile-time constants) ----
    const int F  = in_sizes[3] / HID;          // W0: [F, 16]
    int       N  = (F > 0) ? in_sizes[0] / F : 0;   // x: [N, F]
    const int E  = in_sizes[1] / 2;            // edge_index: [2, E]
    const int DT = in_sizes[7] / HID;          // Wl0: [16, DT]
    if (N > N_MAX) N = N_MAX;                  // fail-soft, never OOB

    // ---- derive NG and output layout from out_size ----
    long long rem = (long long)out_size - (long long)N * DT - (long long)N * 8;
    int NG; bool full_layout;
    if (DT > 0 && rem > 0 && rem % DT == 0 && rem / DT <= 65536) {
        NG = (int)(rem / DT); full_layout = true;    // d_out = concat(out, Z_sum, h)
    } else {
        NG = (DT > 0) ? out_size / DT : 0; full_layout = false;  // d_out = out only
    }
    long long pool_n = 3LL * NG * DT;
    if (pool_n > POOL_CAP) { pool_n = POOL_CAP; }    // fail-soft

    float* out  = (float*)d_out;
    float* outZ = 0;
    float* outH = 0;
    if (full_layout) {
        outZ = out + (size_t)NG * DT;
        outH = outZ + (size_t)N * DT;
    }

    const int nb  = (N + 255) / 256;
    const int nbe = (4LL * E + 255) / 256;
    const int nbz = (N * 4 + 255) / 256;

    // dynamic smem for W0 staging
    size_t smem0 = (size_t)F * HID * sizeof(float);
    if (smem0 > 48 * 1024) {
        cudaFuncSetAttribute(k_gemm0, cudaFuncAttributeMaxDynamicSharedMemorySize, (int)smem0);
    }

    k_init<<<((int)pool_n + 255) / 256, 256>>>((int)pool_n);

    // layer 0
    k_gemm0<<<nb, 256, smem0>>>(x, W0, b0, N, F);
    k_finalize<<<1, 32>>>(HID, g0, be0, N);
    k_bn0<<<nb, 256>>>(N);

    // layer 1
    k_zero_agg<<<nbz, 256>>>(N * 4);
    k_edge<<<nbe, 256>>>(ei, 0, N, E);
    k_gin<HID><<<nb, 256>>>(W1, b1, N);
    k_finalize<<<1, 32>>>(HID, g1, be1, N);
    k_bn1<<<nb, 256>>>(N);

    // layer 2
    k_zero_agg<<<nbz, 256>>>(N * 4);
    k_edge<<<nbe, 256>>>(ei, 1, N, E);
    k_gin<HID2><<<nb, 256>>>(W2, b2, N);
    k_finalize<<<1, 32>>>(HID2, g2, be2, N);
    k_bn2<<<nb, 256>>>(outH, N);

    // fused projections + Z_sum + pools
    dim3 gz((N + CHB - 1) / CHB, (DT + 511) / 512);
    k_bigz<<<gz, 512>>>(Wl0, bl0, Wl1, bl1, Wl2, bl2, bat, outZ, N, DT, NG);
    k_out<<<NG, (DT < 1024 ? DT : 1024)>>>(out, DT, NG);
}

// round 5
// speedup vs baseline: 1.0254x; 1.0254x over previous
#include <cuda_runtime.h>
#include <math.h>

#define HID    16
#define HID2   8
#define BN_EPS 1e-5f

#define N_MAX   1048576
#define E_MAX   8388608
#define NB_MAX  4096            // max scan blocks (N_MAX/256)
#define POOL_CAP (3 * 4194304)

// ---------------- scratch (static __device__) ----------------
__device__ float4   g_pre [N_MAX * 4];
__device__ float4   g_h0  [N_MAX * 4];
__device__ float4   g_h1  [N_MAX * 4];
__device__ float4   g_h2  [N_MAX * 2];
__device__ int      g_cnt [N_MAX];
__device__ int      g_rowptr[N_MAX];
__device__ int      g_woff[N_MAX];
__device__ int      g_bsum[NB_MAX];
__device__ int      g_bpre[NB_MAX];
__device__ int      g_adj [E_MAX];
__device__ float    g_ssum[HID];
__device__ float    g_ssq [HID];
__device__ float    g_scale[HID];
__device__ float    g_shift[HID];
__device__ unsigned g_pool[POOL_CAP];

// ---------------- helpers ----------------
__device__ __forceinline__ float gelu_exact(float v) {
    return 0.5f * v * (1.0f + erff(v * 0.7071067811865476f));
}
__device__ __forceinline__ unsigned enc_f(float f) {
    unsigned u = __float_as_uint(f);
    return (u & 0x80000000u) ? ~u : (u | 0x80000000u);
}
__device__ __forceinline__ float dec_f(unsigned u) {
    return (u & 0x80000000u) ? __uint_as_float(u & 0x7FFFFFFFu)
                             : __uint_as_float(~u);
}
// ---- packed f32x2 (Blackwell) ----
__device__ __forceinline__ unsigned long long pack2(float lo, float hi) {
    unsigned long long r;
    asm("mov.b64 %0, {%1, %2};" : "=l"(r) : "f"(lo), "f"(hi));
    return r;
}
__device__ __forceinline__ void unpack2(unsigned long long v, float& lo, float& hi) {
    asm("mov.b64 {%0, %1}, %2;" : "=f"(lo), "=f"(hi) : "l"(v));
}
__device__ __forceinline__ void ffma2(unsigned long long& d,
                                      unsigned long long a, unsigned long long b) {
    asm("fma.rn.f32x2 %0, %1, %2, %0;" : "+l"(d) : "l"(a), "l"(b));
}

template <int C>
__device__ __forceinline__ void warp_stats(const float* acc) {
#pragma unroll
    for (int j = 0; j < C; j++) {
        float v = acc[j];
        float q = v * v;
#pragma unroll
        for (int o = 16; o > 0; o >>= 1) {
            v += __shfl_xor_sync(0xffffffffu, v, o);
            q += __shfl_xor_sync(0xffffffffu, q, o);
        }
        if ((threadIdx.x & 31) == 0) {
            atomicAdd(&g_ssum[j], v);
            atomicAdd(&g_ssq[j],  q);
        }
    }
}

// ---------------- init: zero pool, stats, degree counters ----------------
__global__ void k_init(int pool_n, int N) {
    int i = blockIdx.x * blockDim.x + threadIdx.x;
    if (i < HID) { g_ssum[i] = 0.f; g_ssq[i] = 0.f; }
    if (i < pool_n) g_pool[i] = 0u;
    if (i < N) g_cnt[i] = 0;
}

// ---------------- layer 0 GEMM (f32x2): pre = x @ W0 + b0, + BN stats ----------------
__global__ __launch_bounds__(256) void k_gemm0(const float* __restrict__ x,
                                               const float* __restrict__ W0,
                                               const float* __restrict__ b0,
                                               int N, int F) {
    extern __shared__ float Ws[];            // F*16 floats (dynamic)
    __shared__ float bs[HID];
    int tid = threadIdx.x;
    int wtot = F * HID;
    for (int i = tid; i < wtot; i += 256) Ws[i] = W0[i];
    if (tid < HID) bs[tid] = b0[tid];
    __syncthreads();

    int r = blockIdx.x * 256 + tid;
    bool act = r < N;
    unsigned long long accp[8];
#pragma unroll
    for (int q = 0; q < 8; q++)
        accp[q] = act ? pack2(bs[2 * q], bs[2 * q + 1]) : pack2(0.f, 0.f);

    if (act) {
        const float4* xr = (const float4*)(x + (size_t)r * F);
        int F4 = F >> 2;
#pragma unroll 4
        for (int c4 = 0; c4 < F4; c4++) {
            float4 xv = __ldg(xr + c4);
#pragma unroll
            for (int u = 0; u < 4; u++) {
                float xs = (&xv.x)[u];
                unsigned long long xx = pack2(xs, xs);
                const ulonglong2* wr = (const ulonglong2*)&Ws[(c4 * 4 + u) * HID];
                ulonglong2 wa = wr[0], wb = wr[1];
                ffma2(accp[0], xx, wa.x); ffma2(accp[1], xx, wa.y);
                ffma2(accp[2], xx, wb.x); ffma2(accp[3], xx, wb.y);
                wa = wr[2]; wb = wr[3];
                ffma2(accp[4], xx, wa.x); ffma2(accp[5], xx, wa.y);
                ffma2(accp[6], xx, wb.x); ffma2(accp[7], xx, wb.y);
            }
        }
        ulonglong2* pr = (ulonglong2*)&g_pre[(size_t)r * 4];
        pr[0] = make_ulonglong2(accp[0], accp[1]);
        pr[1] = make_ulonglong2(accp[2], accp[3]);
        pr[2] = make_ulonglong2(accp[4], accp[5]);
        pr[3] = make_ulonglong2(accp[6], accp[7]);
    }
    float acc[HID];
#pragma unroll
    for (int q = 0; q < 8; q++) unpack2(accp[q], acc[2 * q], acc[2 * q + 1]);
    warp_stats<HID>(acc);
}

// ---------------- BN stats finalize ----------------
__global__ void k_finalize(int C, const float* __restrict__ gam,
                           const float* __restrict__ bet, int N) {
    int j = threadIdx.x;
    if (j < C) {
        float inv_n = 1.0f / (float)N;
        float mean = g_ssum[j] * inv_n;
        float var  = g_ssq[j] * inv_n - mean * mean;
        float istd = rsqrtf(var + BN_EPS);
        float sc   = gam[j] * istd;
        g_scale[j] = sc;
        g_shift[j] = bet[j] - mean * sc;
        g_ssum[j]  = 0.f;
        g_ssq[j]   = 0.f;
    }
}

// ---------------- BN apply kernels ----------------
__global__ void k_bn0(int N) {  // + GELU -> g_h0
    int n = blockIdx.x * blockDim.x + threadIdx.x;
    if (n >= N) return;
#pragma unroll
    for (int q = 0; q < 4; q++) {
        float4 v = g_pre[(size_t)n * 4 + q]; float4 r;
        r.x = gelu_exact(v.x * g_scale[q*4+0] + g_shift[q*4+0]);
        r.y = gelu_exact(v.y * g_scale[q*4+1] + g_shift[q*4+1]);
        r.z = gelu_exact(v.z * g_scale[q*4+2] + g_shift[q*4+2]);
        r.w = gelu_exact(v.w * g_scale[q*4+3] + g_shift[q*4+3]);
        g_h0[(size_t)n * 4 + q] = r;
    }
}

__global__ void k_bn1(int N) {  // no activation -> g_h1
    int n = blockIdx.x * blockDim.x + threadIdx.x;
    if (n >= N) return;
#pragma unroll
    for (int q = 0; q < 4; q++) {
        float4 v = g_pre[(size_t)n * 4 + q]; float4 r;
        r.x = v.x * g_scale[q*4+0] + g_shift[q*4+0];
        r.y = v.y * g_scale[q*4+1] + g_shift[q*4+1];
        r.z = v.z * g_scale[q*4+2] + g_shift[q*4+2];
        r.w = v.w * g_scale[q*4+3] + g_shift[q*4+3];
        g_h1[(size_t)n * 4 + q] = r;
    }
}

__global__ void k_bn2(float* __restrict__ outH, int N) {  // C=8 -> g_h2 (+ out h)
    int n = blockIdx.x * blockDim.x + threadIdx.x;
    if (n >= N) return;
#pragma unroll
    for (int q = 0; q < 2; q++) {
        float4 v = g_pre[(size_t)n * 4 + q]; float4 r;
        r.x = v.x * g_scale[q*4+0] + g_shift[q*4+0];
        r.y = v.y * g_scale[q*4+1] + g_shift[q*4+1];
        r.z = v.z * g_scale[q*4+2] + g_shift[q*4+2];
        r.w = v.w * g_scale[q*4+3] + g_shift[q*4+3];
        g_h2[(size_t)n * 2 + q] = r;
        if (outH) {
            float* o = outH + (size_t)n * 8 + q * 4;
            o[0] = r.x; o[1] = r.y; o[2] = r.z; o[3] = r.w;
        }
    }
}

// ---------------- CSR build ----------------
__global__ void k_hist(const int* __restrict__ ei, int N, int E) {
    int e = blockIdx.x * blockDim.x + threadIdx.x;
    if (e >= E) return;
    int d = __ldg(ei + E + e);
    if ((unsigned)d < (unsigned)N) atomicAdd(&g_cnt[d], 1);
}

#define SCAN_BS 256
__global__ void k_scan1(int n) {     // block-local exclusive scan + block totals
    __shared__ int sh[SCAN_BS];
    int i = blockIdx.x * SCAN_BS + threadIdx.x;
    int v = (i < n) ? g_cnt[i] : 0;
    sh[threadIdx.x] = v;
    __syncthreads();
#pragma unroll
    for (int o = 1; o < SCAN_BS; o <<= 1) {
        int t = (threadIdx.x >= o) ? sh[threadIdx.x - o] : 0;
        __syncthreads();
        sh[threadIdx.x] += t;
        __syncthreads();
    }
    if (i < n) g_rowptr[i] = sh[threadIdx.x] - v;
    if (threadIdx.x == SCAN_BS - 1) g_bsum[blockIdx.x] = sh[threadIdx.x];
}

__global__ void k_scan2(int nb) {    // single block: exclusive scan of block totals
    __shared__ int sh[1024];
    __shared__ int carry;
    if (threadIdx.x == 0) carry = 0;
    __syncthreads();
    for (int base = 0; base < nb; base += 1024) {
        int i = base + threadIdx.x;
        int v = (i < nb) ? g_bsum[i] : 0;
        sh[threadIdx.x] = v;
        __syncthreads();
        for (int o = 1; o < 1024; o <<= 1) {
            int t = (threadIdx.x >= o) ? sh[threadIdx.x - o] : 0;
            __syncthreads();
            sh[threadIdx.x] += t;
            __syncthreads();
        }
        if (i < nb) g_bpre[i] = sh[threadIdx.x] - v + carry;
        __syncthreads();
        if (threadIdx.x == 1023) carry += sh[1023];
        __syncthreads();
    }
}

__global__ void k_scan3(int n) {     // add block prefixes; init write cursors
    int i = blockIdx.x * SCAN_BS + threadIdx.x;
    if (i >= n) return;
    int v = g_rowptr[i] + g_bpre[blockIdx.x];
    g_rowptr[i] = v;
    g_woff[i]   = v;
}

__global__ void k_fill(const int* __restrict__ ei, int N, int E) {
    int e = blockIdx.x * blockDim.x + threadIdx.x;
    if (e >= E) return;
    int s = __ldg(ei + e);
    int d = __ldg(ei + E + e);
    if ((unsigned)s >= (unsigned)N || (unsigned)d >= (unsigned)N) return;
    int pos = atomicAdd(&g_woff[d], 1);
    if (pos < E_MAX) g_adj[pos] = s;
}

// ---------------- GIN: gather + small GEMM + stats (fused) ----------------
// after k_fill: g_rowptr[n] = list start, g_woff[n] = list end
template <int C>
__global__ __launch_bounds__(256) void k_gin(const float* __restrict__ W,
                                             const float* __restrict__ b, int N) {
    __shared__ float Wsh[HID * C];
    __shared__ float bs[C];
    int tid = threadIdx.x;
    for (int i = tid; i < HID * C; i += 256) Wsh[i] = W[i];
    if (tid < C) bs[tid] = b[tid];
    __syncthreads();

    const float4* hin = (C == HID) ? g_h0 : g_h1;
    int n = blockIdx.x * 256 + tid;
    bool act = n < N;
    float acc[C];
#pragma unroll
    for (int j = 0; j < C; j++) acc[j] = 0.f;

    if (act) {
        float4 t0 = hin[(size_t)n * 4 + 0];
        float4 t1 = hin[(size_t)n * 4 + 1];
        float4 t2 = hin[(size_t)n * 4 + 2];
        float4 t3 = hin[(size_t)n * 4 + 3];

        int p   = g_rowptr[n];
        int end = g_woff[n];
        for (; p + 1 < end; p += 2) {
            int s0 = __ldg(g_adj + p);
            int s1 = __ldg(g_adj + p + 1);
            float4 a0 = hin[(size_t)s0 * 4 + 0], b0v = hin[(size_t)s1 * 4 + 0];
            float4 a1 = hin[(size_t)s0 * 4 + 1], b1v = hin[(size_t)s1 * 4 + 1];
            float4 a2 = hin[(size_t)s0 * 4 + 2], b2v = hin[(size_t)s1 * 4 + 2];
            float4 a3 = hin[(size_t)s0 * 4 + 3], b3v = hin[(size_t)s1 * 4 + 3];
            t0.x += a0.x + b0v.x; t0.y += a0.y + b0v.y; t0.z += a0.z + b0v.z; t0.w += a0.w + b0v.w;
            t1.x += a1.x + b1v.x; t1.y += a1.y + b1v.y; t1.z += a1.z + b1v.z; t1.w += a1.w + b1v.w;
            t2.x += a2.x + b2v.x; t2.y += a2.y + b2v.y; t2.z += a2.z + b2v.z; t2.w += a2.w + b2v.w;
            t3.x += a3.x + b3v.x; t3.y += a3.y + b3v.y; t3.z += a3.z + b3v.z; t3.w += a3.w + b3v.w;
        }
        if (p < end) {
            int s0 = __ldg(g_adj + p);
            float4 a0 = hin[(size_t)s0 * 4 + 0];
            float4 a1 = hin[(size_t)s0 * 4 + 1];
            float4 a2 = hin[(size_t)s0 * 4 + 2];
            float4 a3 = hin[(size_t)s0 * 4 + 3];
            t0.x += a0.x; t0.y += a0.y; t0.z += a0.z; t0.w += a0.w;
            t1.x += a1.x; t1.y += a1.y; t1.z += a1.z; t1.w += a1.w;
            t2.x += a2.x; t2.y += a2.y; t2.z += a2.z; t2.w += a2.w;
            t3.x += a3.x; t3.y += a3.y; t3.z += a3.z; t3.w += a3.w;
        }

        float t[HID] = { t0.x, t0.y, t0.z, t0.w, t1.x, t1.y, t1.z, t1.w,
                         t2.x, t2.y, t2.z, t2.w, t3.x, t3.y, t3.z, t3.w };
#pragma unroll
        for (int j = 0; j < C; j++) acc[j] = bs[j];
#pragma unroll
        for (int k = 0; k < HID; k++) {
            float tv = t[k];
#pragma unroll
            for (int j = 0; j < C; j++) acc[j] += tv * Wsh[k * C + j];
        }
#pragma unroll
        for (int q = 0; q < C / 4; q++) {
            g_pre[(size_t)n * 4 + q] =
                make_float4(acc[q*4+0], acc[q*4+1], acc[q*4+2], acc[q*4+3]);
        }
    }
    warp_stats<C>(acc);
}

// ---------------- fused z0/z1/z2 (f32x2): Z_sum write + 3x segment_max ----------------
#define CHB 256
#define STR 260
#define ZTH 256
__global__ __launch_bounds__(ZTH) void k_bigz(const float* __restrict__ Wl0, const float* __restrict__ bl0,
                                              const float* __restrict__ Wl1, const float* __restrict__ bl1,
                                              const float* __restrict__ Wl2, const float* __restrict__ bl2,
                                              const int*   __restrict__ batch,
                                              float* __restrict__ Zs,
                                              int N, int DT, int NG) {
    __shared__ __align__(16) float sh[40 * STR];
    __shared__ int shb[CHB];
    int tid = threadIdx.x;
    int j = blockIdx.y * ZTH + tid;   // feature index
    bool fj = j < DT;

    unsigned long long W0p[HID], W1p[HID], W2p[HID2];
    unsigned long long bb0p = 0, bb1p = 0, bb2p = 0;
    if (fj) {
#pragma unroll
        for (int k = 0; k < HID; k++) {
            float w = Wl0[k * DT + j]; W0p[k] = pack2(w, w);
            float v = Wl1[k * DT + j]; W1p[k] = pack2(v, v);
        }
#pragma unroll
        for (int k = 0; k < HID2; k++) { float w = Wl2[k * DT + j]; W2p[k] = pack2(w, w); }
        float t0 = bl0[j], t1 = bl1[j], t2 = bl2[j];
        bb0p = pack2(t0, t0); bb1p = pack2(t1, t1); bb2p = pack2(t2, t2);
    }

    int n0 = blockIdx.x * CHB;
    int valid = N - n0; if (valid > CHB) valid = CHB;

    const float* h0f = (const float*)g_h0;
    const float* h1f = (const float*)g_h1;
    const float* h2f = (const float*)g_h2;
    for (int idx = tid; idx < valid * 16; idx += ZTH) {
        int n = idx >> 4, k = idx & 15;
        sh[k * STR + n]        = h0f[(size_t)(n0 + n) * 16 + k];
        sh[(16 + k) * STR + n] = h1f[(size_t)(n0 + n) * 16 + k];
    }
    for (int idx = tid; idx < valid * 8; idx += ZTH) {
        int n = idx >> 3, k = idx & 7;
        sh[(32 + k) * STR + n] = h2f[(size_t)(n0 + n) * 8 + k];
    }
    if (tid < valid) shb[tid] = batch[n0 + tid];
    __syncthreads();
    if (!fj) return;

    const float NINF = __int_as_float(0xff800000);
    int cg = -1;
    float m0 = NINF, m1 = NINF, m2 = NINF;

    for (int nl = 0; nl < valid; nl += 4) {
        unsigned long long A0 = bb0p, B0 = bb0p;
        unsigned long long A1 = bb1p, B1 = bb1p;
        unsigned long long A2 = bb2p, B2 = bb2p;
#pragma unroll
        for (int k = 0; k < HID; k++) {
            ulonglong2 hv = *(const ulonglong2*)&sh[k * STR + nl];
            ffma2(A0, hv.x, W0p[k]); ffma2(B0, hv.y, W0p[k]);
        }
#pragma unroll
        for (int k = 0; k < HID; k++) {
            ulonglong2 hv = *(const ulonglong2*)&sh[(16 + k) * STR + nl];
            ffma2(A1, hv.x, W1p[k]); ffma2(B1, hv.y, W1p[k]);
        }
#pragma unroll
        for (int k = 0; k < HID2; k++) {
            ulonglong2 hv = *(const ulonglong2*)&sh[(32 + k) * STR + nl];
            ffma2(A2, hv.x, W2p[k]); ffma2(B2, hv.y, W2p[k]);
        }
        float a0[4], a1[4], a2[4];
        unpack2(A0, a0[0], a0[1]); unpack2(B0, a0[2], a0[3]);
        unpack2(A1, a1[0], a1[1]); unpack2(B1, a1[2], a1[3]);
        unpack2(A2, a2[0], a2[1]); unpack2(B2, a2[2], a2[3]);
#pragma unroll
        for (int i = 0; i < 4; i++) {
            if (nl + i >= valid) break;
            float z0 = gelu_exact(a0[i]);
            float z1 = a1[i], z2 = a2[i];
            if (Zs) Zs[(size_t)(n0 + nl + i) * DT + j] = z0 + z1 + z2;
            int g = shb[nl + i];
            if (g != cg) {
                if ((unsigned)cg < (unsigned)NG) {
                    atomicMax(&g_pool[(size_t)cg * DT + j],            enc_f(m0));
                    atomicMax(&g_pool[((size_t)NG + cg) * DT + j],     enc_f(m1));
                    atomicMax(&g_pool[((size_t)2 * NG + cg) * DT + j], enc_f(m2));
                }
                cg = g; m0 = NINF; m1 = NINF; m2 = NINF;
            }
            m0 = fmaxf(m0, z0); m1 = fmaxf(m1, z1); m2 = fmaxf(m2, z2);
        }
    }
    if ((unsigned)cg < (unsigned)NG) {
        atomicMax(&g_pool[(size_t)cg * DT + j],            enc_f(m0));
        atomicMax(&g_pool[((size_t)NG + cg) * DT + j],     enc_f(m1));
        atomicMax(&g_pool[((size_t)2 * NG + cg) * DT + j], enc_f(m2));
    }
}

// ---------------- pooled output ----------------
__global__ void k_out(float* __restrict__ out, int DT, int NG) {
    int g = blockIdx.x;
    for (int j = threadIdx.x; j < DT; j += blockDim.x) {
        out[(size_t)g * DT + j] = dec_f(g_pool[(size_t)g * DT + j])
                                + dec_f(g_pool[((size_t)NG + g) * DT + j])
                                + dec_f(g_pool[((size_t)2 * NG + g) * DT + j]);
    }
}

// ---------------- launch ----------------
extern "C" void kernel_launch(void* const* d_in, const int* in_sizes, int n_in,
                              void* d_out, int out_size) {
    const float* x   = (const float*)d_in[0];
    const int*   ei  = (const int*)  d_in[1];
    const int*   bat = (const int*)  d_in[2];
    const float* W0  = (const float*)d_in[3];
    const float* b0  = (const float*)d_in[4];
    const float* g0  = (const float*)d_in[5];
    const float* be0 = (const float*)d_in[6];
    const float* Wl0 = (const float*)d_in[7];
    const float* bl0 = (const float*)d_in[8];
    const float* W1  = (const float*)d_in[9];
    const float* b1  = (const float*)d_in[10];
    const float* g1  = (const float*)d_in[11];
    const float* be1 = (const float*)d_in[12];
    const float* Wl1 = (const float*)d_in[13];
    const float* bl1 = (const float*)d_in[14];
    const float* W2  = (const float*)d_in[15];
    const float* b2  = (const float*)d_in[16];
    const float* g2  = (const float*)d_in[17];
    const float* be2 = (const float*)d_in[18];
    const float* Wl2 = (const float*)d_in[19];
    const float* bl2 = (const float*)d_in[20];

    // ---- shapes from in_sizes ----
    const int F  = in_sizes[3] / HID;
    int       N  = (F > 0) ? in_sizes[0] / F : 0;
    int       E  = in_sizes[1] / 2;
    const int DT = in_sizes[7] / HID;
    if (N > N_MAX) N = N_MAX;
    if (E > E_MAX) E = E_MAX;

    // ---- NG + output layout from out_size ----
    long long rem = (long long)out_size - (long long)N * DT - (long long)N * 8;
    int NG; bool full_layout;
    if (DT > 0 && rem > 0 && rem % DT == 0 && rem / DT <= 65536) {
        NG = (int)(rem / DT); full_layout = true;
    } else {
        NG = (DT > 0) ? out_size / DT : 0; full_layout = false;
    }
    long long pool_n = 3LL * NG * DT;
    if (pool_n > POOL_CAP) pool_n = POOL_CAP;

    float* out  = (float*)d_out;
    float* outZ = 0;
    float* outH = 0;
    if (full_layout) {
        outZ = out + (size_t)NG * DT;
        outH = outZ + (size_t)N * DT;
    }

    const int nb  = (N + 255) / 256;
    const int nbe = (E + 255) / 256;
    const int nsb = (N + SCAN_BS - 1) / SCAN_BS;

    size_t smem0 = (size_t)F * HID * sizeof(float);
    if (smem0 > 48 * 1024) {
        cudaFuncSetAttribute(k_gemm0, cudaFuncAttributeMaxDynamicSharedMemorySize, (int)smem0);
    }

    long long init_n = pool_n > N ? pool_n : N;
    k_init<<<((int)init_n + 255) / 256, 256>>>((int)pool_n, N);

    // layer 0 dense chain
    k_gemm0<<<nb, 256, smem0>>>(x, W0, b0, N, F);
    k_finalize<<<1, 32>>>(HID, g0, be0, N);
    k_bn0<<<nb, 256>>>(N);

    // CSR build (once, reused by both GIN layers)
    k_hist<<<nbe, 256>>>(ei, N, E);
    k_scan1<<<nsb, SCAN_BS>>>(N);
    k_scan2<<<1, 1024>>>(nsb);
    k_scan3<<<nsb, SCAN_BS>>>(N);
    k_fill<<<nbe, 256>>>(ei, N, E);

    // layer 1
    k_gin<HID><<<nb, 256>>>(W1, b1, N);
    k_finalize<<<1, 32>>>(HID, g1, be1, N);
    k_bn1<<<nb, 256>>>(N);

    // layer 2
    k_gin<HID2><<<nb, 256>>>(W2, b2, N);
    k_finalize<<<1, 32>>>(HID2, g2, be2, N);
    k_bn2<<<nb, 256>>>(outH, N);

    // fused projections + Z_sum + pools
    dim3 gz((N + CHB - 1) / CHB, (DT + ZTH - 1) / ZTH);
    k_bigz<<<gz, ZTH>>>(Wl0, bl0, Wl1, bl1, Wl2, bl2, bat, outZ, N, DT, NG);
    k_out<<<NG, (DT < 1024 ? DT : 1024)>>>(out, DT, NG);
}